// round 12
// baseline (speedup 1.0000x reference)
#include <cuda_runtime.h>
#include <cuda_bf16.h>
#include <cstdint>

#define Bn      128
#define DMODEL  1024
#define DMEM    64
#define NH      16
#define NMEM    4096

// ================= helpers =================
__device__ __forceinline__ uint32_t smem_u32(const void* p) {
    uint32_t a;
    asm("{ .reg .u64 t; cvta.to.shared.u64 t, %1; cvt.u32.u64 %0, t; }"
        : "=r"(a) : "l"(p));
    return a;
}
__device__ __forceinline__ void ldsm4(uint32_t* r, uint32_t a) {
    asm volatile("ldmatrix.sync.aligned.m8n8.x4.shared.b16 {%0,%1,%2,%3}, [%4];"
                 : "=r"(r[0]), "=r"(r[1]), "=r"(r[2]), "=r"(r[3]) : "r"(a));
}
__device__ __forceinline__ void ldsm4t(uint32_t* r, uint32_t a) {
    asm volatile("ldmatrix.sync.aligned.m8n8.x4.trans.shared.b16 {%0,%1,%2,%3}, [%4];"
                 : "=r"(r[0]), "=r"(r[1]), "=r"(r[2]), "=r"(r[3]) : "r"(a));
}
__device__ __forceinline__ void mma16816(float* c, const uint32_t* a,
                                         uint32_t b0, uint32_t b1) {
    asm volatile(
        "mma.sync.aligned.m16n8k16.row.col.f32.bf16.bf16.f32 "
        "{%0,%1,%2,%3}, {%4,%5,%6,%7}, {%8,%9}, {%0,%1,%2,%3};"
        : "+f"(c[0]), "+f"(c[1]), "+f"(c[2]), "+f"(c[3])
        : "r"(a[0]), "r"(a[1]), "r"(a[2]), "r"(a[3]), "r"(b0), "r"(b1));
}
__device__ __forceinline__ unsigned b2u(__nv_bfloat162 v) {
    return *reinterpret_cast<unsigned*>(&v);
}
__device__ __forceinline__ void split2(float2 f, uint32_t& hi, uint32_t& lo) {
    __nv_bfloat162 h = __float22bfloat162_rn(f);
    float2 hf = __bfloat1622float2(h);
    __nv_bfloat162 l = __float22bfloat162_rn(make_float2(f.x - hf.x, f.y - hf.y));
    hi = b2u(h);
    lo = b2u(l);
}

// ================= scratch =================
__device__ float g_qa[Bn * DMODEL];
__device__ float g_attn[Bn * DMODEL];
__device__ float g_gp[8 * Bn * DMODEL];      // split-K partials (4 MB)

// ============================================================
// Stage 1 + attn read, fused (HMMA). Per batch b:
//   matrix[d][e] = sum_n relu(mem+addr)[n][d] * mem[n][e]   (smem only)
//   norm[d]      = sum_n k[n][d]
//   attn[h][e]   = (qa[h] . matrix[:,e]) / (qa[h] . norm + 1e-5)
// 512 threads = 16 warps: (wd 0..3) x (we 0..1) x (wk 0..1 k-split).
// Double-buffered bf16 tiles [n=64][feat=64] (kh,kl,mh,ml), XOR-swizzled.
// ============================================================
#define S1_SMEM 65536

__global__ __launch_bounds__(512, 1) void stage1_fused(
    const float* __restrict__ mem, const float* __restrict__ addr)
{
    extern __shared__ __align__(1024) char sm[];
    const uint32_t sb = smem_u32(sm);
    const int b = blockIdx.x, tid = threadIdx.x;
    const int lane = tid & 31, w = tid >> 5;

    // tile offsets within one buffer; buffer stride 32768
    const uint32_t KH = 0, KL = 8192, MH = 16384, ML = 24576;

    // ---- conversion mapping: thread -> (n row, 8-float d group) ----
    const int n1 = tid >> 3;                 // 0..63
    const int dg = (tid & 7) << 3;           // float col base, 0..56
    const uint32_t swc = ((uint32_t)(n1 * 128 + dg * 2)) ^ ((uint32_t)(n1 & 7) << 4);

    // ---- mma mapping ----
    const int wd = w & 3, we = (w >> 2) & 1, wk = w >> 3;
    const int m0 = wd * 16;                  // d rows
    const int e0 = we * 32;                  // e cols
    const uint32_t lm = (uint32_t)(lane & 7) << 4;
    const int rA = (lane & 7) + 8 * (lane >> 4);
    const int cA = m0 + 8 * ((lane >> 3) & 1);
    const uint32_t swA = ((uint32_t)(rA * 128 + cA * 2)) ^ lm;
    const int rB = (lane & 7) + 8 * ((lane >> 3) & 1);
    const int cB = e0 + 8 * (lane >> 4);
    const uint32_t swB0 = ((uint32_t)(rB * 128 + cB * 2)) ^ lm;
    const uint32_t swB1 = ((uint32_t)(rB * 128 + (cB + 16) * 2)) ^ lm;

    float acc[4][4];
#pragma unroll
    for (int i = 0; i < 4; i++)
#pragma unroll
        for (int j = 0; j < 4; j++) acc[i][j] = 0.f;

    float nacc[8];
#pragma unroll
    for (int i = 0; i < 8; i++) nacc[i] = 0.f;

    const float* mb = mem + (size_t)b * NMEM * DMEM;

    float4 m4[2], a4[2];
    auto ldg_chunk = [&](int ch) {
        const float* pm = mb   + ((size_t)ch * 64 + n1) * DMEM + dg;
        const float* pa = addr + ((size_t)ch * 64 + n1) * DMEM + dg;
        m4[0] = *(const float4*)pm;
        m4[1] = *(const float4*)(pm + 4);
        a4[0] = *(const float4*)pa;
        a4[1] = *(const float4*)(pa + 4);
    };
    auto cvt_store = [&](int buf) {
        float mv[8], kv[8];
#pragma unroll
        for (int j = 0; j < 2; j++) {
            mv[4*j+0] = m4[j].x; mv[4*j+1] = m4[j].y;
            mv[4*j+2] = m4[j].z; mv[4*j+3] = m4[j].w;
            kv[4*j+0] = fmaxf(m4[j].x + a4[j].x, 0.f);
            kv[4*j+1] = fmaxf(m4[j].y + a4[j].y, 0.f);
            kv[4*j+2] = fmaxf(m4[j].z + a4[j].z, 0.f);
            kv[4*j+3] = fmaxf(m4[j].w + a4[j].w, 0.f);
        }
#pragma unroll
        for (int i = 0; i < 8; i++) nacc[i] += kv[i];
        uint32_t kh[4], kl[4], mh[4], ml[4];
#pragma unroll
        for (int p = 0; p < 4; p++) {
            split2(make_float2(kv[2*p], kv[2*p+1]), kh[p], kl[p]);
            split2(make_float2(mv[2*p], mv[2*p+1]), mh[p], ml[p]);
        }
        char* base = sm + buf * 32768;
        *(uint4*)(base + KH + swc) = make_uint4(kh[0], kh[1], kh[2], kh[3]);
        *(uint4*)(base + KL + swc) = make_uint4(kl[0], kl[1], kl[2], kl[3]);
        *(uint4*)(base + MH + swc) = make_uint4(mh[0], mh[1], mh[2], mh[3]);
        *(uint4*)(base + ML + swc) = make_uint4(ml[0], ml[1], ml[2], ml[3]);
    };

    ldg_chunk(0);
    cvt_store(0);
    __syncthreads();

    for (int ch = 0; ch < NMEM / 64; ch++) {
        const uint32_t tb = sb + (uint32_t)(ch & 1) * 32768;
        if (ch + 1 < NMEM / 64) ldg_chunk(ch + 1);

        // ---- mma: this warp handles ksteps {2*wk, 2*wk+1} ----
#pragma unroll
        for (int ks = 0; ks < 2; ks++) {
            const uint32_t ko = 2048u * (2 * wk + ks);
            uint32_t ah[4], al[4], bh0[4], bh1[4], bl0[4], bl1[4];
            ldsm4t(ah,  tb + KH + swA + ko);
            ldsm4t(al,  tb + KL + swA + ko);
            ldsm4t(bh0, tb + MH + swB0 + ko);
            ldsm4t(bh1, tb + MH + swB1 + ko);
            ldsm4t(bl0, tb + ML + swB0 + ko);
            ldsm4t(bl1, tb + ML + swB1 + ko);
            mma16816(acc[0], ah, bh0[0], bh0[1]);
            mma16816(acc[1], ah, bh0[2], bh0[3]);
            mma16816(acc[2], ah, bh1[0], bh1[1]);
            mma16816(acc[3], ah, bh1[2], bh1[3]);
            mma16816(acc[0], ah, bl0[0], bl0[1]);
            mma16816(acc[1], ah, bl0[2], bl0[3]);
            mma16816(acc[2], ah, bl1[0], bl1[1]);
            mma16816(acc[3], ah, bl1[2], bl1[3]);
            mma16816(acc[0], al, bh0[0], bh0[1]);
            mma16816(acc[1], al, bh0[2], bh0[3]);
            mma16816(acc[2], al, bh1[0], bh1[1]);
            mma16816(acc[3], al, bh1[2], bh1[3]);
        }

        if (ch + 1 < NMEM / 64) cvt_store((ch + 1) & 1);
        __syncthreads();
    }

    // ================= fused epilogue =================
    // smem reuse (all tiles dead): mat[64][66] @0, npart[64][66] @32768,
    // qa[16][64] @49664, norm[64] @53760, den[16] @54016
    float* s_mat = (float*)sm;
    float* s_np  = (float*)(sm + 32768);
    float* s_qa  = (float*)(sm + 49664);
    float* s_nr  = (float*)(sm + 53760);
    float* s_dn  = (float*)(sm + 54016);

    const int cr0 = m0 + (lane >> 2);
    const int cc0 = e0 + (lane & 3) * 2;

    // step A: wk=0 accs -> mat; norm partials; qa copy
    if (wk == 0) {
#pragma unroll
        for (int j = 0; j < 4; j++) {
            int c = cc0 + 8 * j;
            s_mat[cr0 * 66 + c]           = acc[j][0];
            s_mat[cr0 * 66 + c + 1]       = acc[j][1];
            s_mat[(cr0 + 8) * 66 + c]     = acc[j][2];
            s_mat[(cr0 + 8) * 66 + c + 1] = acc[j][3];
        }
    }
#pragma unroll
    for (int i = 0; i < 8; i++) s_np[n1 * 66 + dg + i] = nacc[i];
    if (tid < 256)
        ((float4*)s_qa)[tid] = ((const float4*)(g_qa + (size_t)b * DMODEL))[tid];
    __syncthreads();

    // step B: wk=1 accs merge; norm reduce
    if (wk == 1) {
#pragma unroll
        for (int j = 0; j < 4; j++) {
            int c = cc0 + 8 * j;
            s_mat[cr0 * 66 + c]           += acc[j][0];
            s_mat[cr0 * 66 + c + 1]       += acc[j][1];
            s_mat[(cr0 + 8) * 66 + c]     += acc[j][2];
            s_mat[(cr0 + 8) * 66 + c + 1] += acc[j][3];
        }
    }
    if (tid < DMEM) {
        float s = 0.f;
#pragma unroll 8
        for (int n = 0; n < 64; n++) s += s_np[n * 66 + tid];
        s_nr[tid] = s;
    }
    __syncthreads();

    // step C: denominators
    if (tid < NH) {
        float s = 0.f;
#pragma unroll 8
        for (int d = 0; d < DMEM; d++) s += s_qa[tid * DMEM + d] * s_nr[d];
        s_dn[tid] = s + 1e-5f;
    }
    __syncthreads();

    // step D: attn = qa @ mat / den   (each thread: heads h0 and h0+8, col e)
    {
        const int e = tid & 63;
        const int h0 = tid >> 6;          // 0..7
        float a0 = 0.f, a1 = 0.f;
#pragma unroll 8
        for (int d = 0; d < DMEM; d++) {
            float mv = s_mat[d * 66 + e];
            a0 += s_qa[h0 * DMEM + d] * mv;
            a1 += s_qa[(h0 + 8) * DMEM + d] * mv;
        }
        float* oa = g_attn + (size_t)b * DMODEL;
        oa[h0 * DMEM + e]       = a0 / s_dn[h0];
        oa[(h0 + 8) * DMEM + e] = a1 / s_dn[h0 + 8];
    }
}

// ============================================================
// HMMA split-K NT GEMM (known-good from R10)
// ============================================================
#define GA_H 0
#define GA_L 32768
#define GW_H 65536
#define GW_L 81920
#define G_SMEM 98304

__global__ __launch_bounds__(256, 1) void gemm_mma(
    const float* __restrict__ A_ext, const float* __restrict__ W, int mode)
{
    extern __shared__ __align__(1024) char sm[];
    const uint32_t sb = smem_u32(sm);
    const float* A = mode ? g_attn : A_ext;

    const int tid = threadIdx.x, lane = tid & 31, w = tid >> 5;
    const int bn = blockIdx.x * 64;
    const int kc0 = blockIdx.y * 128;

#pragma unroll
    for (int i = 0; i < 8; i++) {
        int item = tid + 256 * i;
        int row = item >> 4, c8 = item & 15;
        const float* p = A + (size_t)row * DMODEL + kc0 + c8 * 8;
        float4 f0 = *(const float4*)p, f1 = *(const float4*)(p + 4);
        uint32_t h[4], l[4];
        split2(make_float2(f0.x, f0.y), h[0], l[0]);
        split2(make_float2(f0.z, f0.w), h[1], l[1]);
        split2(make_float2(f1.x, f1.y), h[2], l[2]);
        split2(make_float2(f1.z, f1.w), h[3], l[3]);
        uint32_t off = (uint32_t)(row * 256 + c8 * 16);
        uint32_t sw = off ^ ((off >> 4) & 0x70);
        *(uint4*)(sm + GA_H + sw) = make_uint4(h[0], h[1], h[2], h[3]);
        *(uint4*)(sm + GA_L + sw) = make_uint4(l[0], l[1], l[2], l[3]);
    }
#pragma unroll
    for (int i = 0; i < 4; i++) {
        int item = tid + 256 * i;
        int row = item >> 4, c8 = item & 15;
        const float* p = W + (size_t)(bn + row) * DMODEL + kc0 + c8 * 8;
        float4 f0 = *(const float4*)p, f1 = *(const float4*)(p + 4);
        uint32_t h[4], l[4];
        split2(make_float2(f0.x, f0.y), h[0], l[0]);
        split2(make_float2(f0.z, f0.w), h[1], l[1]);
        split2(make_float2(f1.x, f1.y), h[2], l[2]);
        split2(make_float2(f1.z, f1.w), h[3], l[3]);
        uint32_t off = (uint32_t)(row * 256 + c8 * 16);
        uint32_t sw = off ^ ((off >> 4) & 0x70);
        *(uint4*)(sm + GW_H + sw) = make_uint4(h[0], h[1], h[2], h[3]);
        *(uint4*)(sm + GW_L + sw) = make_uint4(l[0], l[1], l[2], l[3]);
    }
    __syncthreads();

    const int m0 = w * 16;
    float acc[8][4];
#pragma unroll
    for (int i = 0; i < 8; i++)
#pragma unroll
        for (int j = 0; j < 4; j++) acc[i][j] = 0.f;

    const int rA = (lane & 7) + 8 * ((lane >> 3) & 1);
    const uint32_t baseA = (uint32_t)((m0 + rA) * 256 + (lane >> 4) * 16);
    const uint32_t maskA = (uint32_t)(lane & 7) << 4;
    const int rBl = (lane & 7) + 8 * (lane >> 4);
    const uint32_t hB = ((uint32_t)(lane >> 3) & 1) * 16;
    const uint32_t maskB = (uint32_t)(lane & 7) << 4;

#pragma unroll
    for (int ks = 0; ks < 8; ks++) {
        uint32_t swAa = (baseA + ks * 32) ^ maskA;
        uint32_t ah[4], al[4];
        ldsm4(ah, sb + GA_H + swAa);
        ldsm4(al, sb + GA_L + swAa);
#pragma unroll
        for (int j = 0; j < 4; j++) {
            uint32_t offB = (uint32_t)((16 * j + rBl) * 256 + ks * 32) + hB;
            uint32_t swB = offB ^ maskB;
            uint32_t wh[4], wl[4];
            ldsm4(wh, sb + GW_H + swB);
            ldsm4(wl, sb + GW_L + swB);
            mma16816(acc[2*j],     ah, wh[0], wh[1]);
            mma16816(acc[2*j + 1], ah, wh[2], wh[3]);
            mma16816(acc[2*j],     ah, wl[0], wl[1]);
            mma16816(acc[2*j + 1], ah, wl[2], wl[3]);
            mma16816(acc[2*j],     al, wh[0], wh[1]);
            mma16816(acc[2*j + 1], al, wh[2], wh[3]);
        }
    }

    float* P = g_gp + (size_t)blockIdx.y * (Bn * DMODEL);
    int r0 = m0 + (lane >> 2);
    int c0 = bn + (lane & 3) * 2;
#pragma unroll
    for (int jj = 0; jj < 8; jj++) {
        int c = c0 + 8 * jj;
        *(float2*)(P + (size_t)r0 * DMODEL + c)       = make_float2(acc[jj][0], acc[jj][1]);
        *(float2*)(P + (size_t)(r0 + 8) * DMODEL + c) = make_float2(acc[jj][2], acc[jj][3]);
    }
}

__global__ __launch_bounds__(256) void gemm_reduce(
    const float* __restrict__ bias, float* __restrict__ C_ext, int mode)
{
    int idx = blockIdx.x * 256 + threadIdx.x;
    float v = bias[idx & (DMODEL - 1)];
#pragma unroll
    for (int s = 0; s < 8; s++) v += g_gp[(size_t)s * Bn * DMODEL + idx];
    if (mode == 0) g_qa[idx] = fmaxf(v, 0.f);
    else           C_ext[idx] = v;
}

// ============================================================
extern "C" void kernel_launch(void* const* d_in, const int* in_sizes, int n_in,
                              void* d_out, int out_size)
{
    (void)in_sizes; (void)n_in; (void)out_size;
    const float* query     = (const float*)d_in[0];
    const float* addresses = (const float*)d_in[1];
    const float* memories  = (const float*)d_in[2];
    const float* Wq        = (const float*)d_in[3];
    const float* bq        = (const float*)d_in[4];
    const float* Wm        = (const float*)d_in[5];
    const float* bm        = (const float*)d_in[6];
    float* out = (float*)d_out;

    cudaFuncSetAttribute(gemm_mma, cudaFuncAttributeMaxDynamicSharedMemorySize, G_SMEM);
    cudaFuncSetAttribute(stage1_fused, cudaFuncAttributeMaxDynamicSharedMemorySize, S1_SMEM);

    // qa = relu(query @ Wq^T + bq)
    gemm_mma<<<dim3(16, 8), 256, G_SMEM>>>(query, Wq, 0);
    gemm_reduce<<<512, 256>>>(bq, nullptr, 0);
    // matrix + normalizer + attn (fused)
    stage1_fused<<<Bn, 512, S1_SMEM>>>(memories, addresses);
    // out = attn @ Wm^T + bm
    gemm_mma<<<dim3(16, 8), 256, G_SMEM>>>(nullptr, Wm, 1);
    gemm_reduce<<<512, 256>>>(bm, out, 1);
}

// round 13
// speedup vs baseline: 1.0037x; 1.0037x over previous
#include <cuda_runtime.h>
#include <cuda_bf16.h>
#include <cstdint>

#define Bn      128
#define DMODEL  1024
#define DMEM    64
#define NH      16
#define NMEM    4096

// ================= helpers =================
__device__ __forceinline__ uint32_t smem_u32(const void* p) {
    uint32_t a;
    asm("{ .reg .u64 t; cvta.to.shared.u64 t, %1; cvt.u32.u64 %0, t; }"
        : "=r"(a) : "l"(p));
    return a;
}
__device__ __forceinline__ void ldsm4(uint32_t* r, uint32_t a) {
    asm volatile("ldmatrix.sync.aligned.m8n8.x4.shared.b16 {%0,%1,%2,%3}, [%4];"
                 : "=r"(r[0]), "=r"(r[1]), "=r"(r[2]), "=r"(r[3]) : "r"(a));
}
__device__ __forceinline__ void ldsm4t(uint32_t* r, uint32_t a) {
    asm volatile("ldmatrix.sync.aligned.m8n8.x4.trans.shared.b16 {%0,%1,%2,%3}, [%4];"
                 : "=r"(r[0]), "=r"(r[1]), "=r"(r[2]), "=r"(r[3]) : "r"(a));
}
__device__ __forceinline__ void mma16816(float* c, const uint32_t* a,
                                         uint32_t b0, uint32_t b1) {
    asm volatile(
        "mma.sync.aligned.m16n8k16.row.col.f32.bf16.bf16.f32 "
        "{%0,%1,%2,%3}, {%4,%5,%6,%7}, {%8,%9}, {%0,%1,%2,%3};"
        : "+f"(c[0]), "+f"(c[1]), "+f"(c[2]), "+f"(c[3])
        : "r"(a[0]), "r"(a[1]), "r"(a[2]), "r"(a[3]), "r"(b0), "r"(b1));
}
__device__ __forceinline__ unsigned b2u(__nv_bfloat162 v) {
    return *reinterpret_cast<unsigned*>(&v);
}
__device__ __forceinline__ void split2(float2 f, uint32_t& hi, uint32_t& lo) {
    __nv_bfloat162 h = __float22bfloat162_rn(f);
    float2 hf = __bfloat1622float2(h);
    __nv_bfloat162 l = __float22bfloat162_rn(make_float2(f.x - hf.x, f.y - hf.y));
    hi = b2u(h);
    lo = b2u(l);
}

// ================= scratch =================
__device__ float g_qa[Bn * DMODEL];
__device__ float g_attn[Bn * DMODEL];
__device__ float g_gp[8 * Bn * DMODEL];      // split-K partials (4 MB)

// ============================================================
// Stage 1 + attn read, fused (HMMA). Per batch b:
//   matrix[d][e] = sum_n relu(mem+addr)[n][d] * mem[n][e]   (smem only)
//   norm[d]      = sum_n k[n][d]
//   attn[h][e]   = (qa[h] . matrix[:,e]) / (qa[h] . norm + 1e-5)
// 512 threads = 16 warps: (wd 0..3) x (we 0..1) x (wk 0..1 k-split).
// Double-buffered bf16 tiles [n=64][feat=64] (kh,kl,mh,ml), XOR-swizzled.
// ============================================================
#define S1_SMEM 65536

__global__ __launch_bounds__(512, 1) void stage1_fused(
    const float* __restrict__ mem, const float* __restrict__ addr)
{
    extern __shared__ __align__(1024) char sm[];
    const uint32_t sb = smem_u32(sm);
    const int b = blockIdx.x, tid = threadIdx.x;
    const int lane = tid & 31, w = tid >> 5;

    // tile offsets within one buffer; buffer stride 32768
    const uint32_t KH = 0, KL = 8192, MH = 16384, ML = 24576;

    // ---- conversion mapping: thread -> (n row, 8-float d group) ----
    const int n1 = tid >> 3;                 // 0..63
    const int dg = (tid & 7) << 3;           // float col base, 0..56
    const uint32_t swc = ((uint32_t)(n1 * 128 + dg * 2)) ^ ((uint32_t)(n1 & 7) << 4);

    // ---- mma mapping ----
    const int wd = w & 3, we = (w >> 2) & 1, wk = w >> 3;
    const int m0 = wd * 16;                  // d rows
    const int e0 = we * 32;                  // e cols
    const uint32_t lm = (uint32_t)(lane & 7) << 4;
    const int rA = (lane & 7) + 8 * (lane >> 4);
    const int cA = m0 + 8 * ((lane >> 3) & 1);
    const uint32_t swA = ((uint32_t)(rA * 128 + cA * 2)) ^ lm;
    const int rB = (lane & 7) + 8 * ((lane >> 3) & 1);
    const int cB = e0 + 8 * (lane >> 4);
    const uint32_t swB0 = ((uint32_t)(rB * 128 + cB * 2)) ^ lm;
    const uint32_t swB1 = ((uint32_t)(rB * 128 + (cB + 16) * 2)) ^ lm;

    float acc[4][4];
#pragma unroll
    for (int i = 0; i < 4; i++)
#pragma unroll
        for (int j = 0; j < 4; j++) acc[i][j] = 0.f;

    float nacc[8];
#pragma unroll
    for (int i = 0; i < 8; i++) nacc[i] = 0.f;

    const float* mb = mem + (size_t)b * NMEM * DMEM;

    float4 m4[2], a4[2];
    auto ldg_chunk = [&](int ch) {
        const float* pm = mb   + ((size_t)ch * 64 + n1) * DMEM + dg;
        const float* pa = addr + ((size_t)ch * 64 + n1) * DMEM + dg;
        m4[0] = *(const float4*)pm;
        m4[1] = *(const float4*)(pm + 4);
        a4[0] = *(const float4*)pa;
        a4[1] = *(const float4*)(pa + 4);
    };
    auto cvt_store = [&](int buf) {
        float mv[8], kv[8];
#pragma unroll
        for (int j = 0; j < 2; j++) {
            mv[4*j+0] = m4[j].x; mv[4*j+1] = m4[j].y;
            mv[4*j+2] = m4[j].z; mv[4*j+3] = m4[j].w;
            kv[4*j+0] = fmaxf(m4[j].x + a4[j].x, 0.f);
            kv[4*j+1] = fmaxf(m4[j].y + a4[j].y, 0.f);
            kv[4*j+2] = fmaxf(m4[j].z + a4[j].z, 0.f);
            kv[4*j+3] = fmaxf(m4[j].w + a4[j].w, 0.f);
        }
#pragma unroll
        for (int i = 0; i < 8; i++) nacc[i] += kv[i];
        uint32_t kh[4], kl[4], mh[4], ml[4];
#pragma unroll
        for (int p = 0; p < 4; p++) {
            split2(make_float2(kv[2*p], kv[2*p+1]), kh[p], kl[p]);
            split2(make_float2(mv[2*p], mv[2*p+1]), mh[p], ml[p]);
        }
        char* base = sm + buf * 32768;
        *(uint4*)(base + KH + swc) = make_uint4(kh[0], kh[1], kh[2], kh[3]);
        *(uint4*)(base + KL + swc) = make_uint4(kl[0], kl[1], kl[2], kl[3]);
        *(uint4*)(base + MH + swc) = make_uint4(mh[0], mh[1], mh[2], mh[3]);
        *(uint4*)(base + ML + swc) = make_uint4(ml[0], ml[1], ml[2], ml[3]);
    };

    ldg_chunk(0);
    cvt_store(0);
    __syncthreads();

    for (int ch = 0; ch < NMEM / 64; ch++) {
        const uint32_t tb = sb + (uint32_t)(ch & 1) * 32768;
        if (ch + 1 < NMEM / 64) ldg_chunk(ch + 1);

        // ---- mma: this warp handles ksteps {2*wk, 2*wk+1} ----
#pragma unroll
        for (int ks = 0; ks < 2; ks++) {
            const uint32_t ko = 2048u * (2 * wk + ks);
            uint32_t ah[4], al[4], bh0[4], bh1[4], bl0[4], bl1[4];
            ldsm4t(ah,  tb + KH + swA + ko);
            ldsm4t(al,  tb + KL + swA + ko);
            ldsm4t(bh0, tb + MH + swB0 + ko);
            ldsm4t(bh1, tb + MH + swB1 + ko);
            ldsm4t(bl0, tb + ML + swB0 + ko);
            ldsm4t(bl1, tb + ML + swB1 + ko);
            mma16816(acc[0], ah, bh0[0], bh0[1]);
            mma16816(acc[1], ah, bh0[2], bh0[3]);
            mma16816(acc[2], ah, bh1[0], bh1[1]);
            mma16816(acc[3], ah, bh1[2], bh1[3]);
            mma16816(acc[0], ah, bl0[0], bl0[1]);
            mma16816(acc[1], ah, bl0[2], bl0[3]);
            mma16816(acc[2], ah, bl1[0], bl1[1]);
            mma16816(acc[3], ah, bl1[2], bl1[3]);
            mma16816(acc[0], al, bh0[0], bh0[1]);
            mma16816(acc[1], al, bh0[2], bh0[3]);
            mma16816(acc[2], al, bh1[0], bh1[1]);
            mma16816(acc[3], al, bh1[2], bh1[3]);
        }

        if (ch + 1 < NMEM / 64) cvt_store((ch + 1) & 1);
        __syncthreads();
    }

    // ================= fused epilogue =================
    // smem reuse (all tiles dead): mat[64][66] @0, npart[64][66] @32768,
    // qa[16][64] @49664, norm[64] @53760, den[16] @54016
    float* s_mat = (float*)sm;
    float* s_np  = (float*)(sm + 32768);
    float* s_qa  = (float*)(sm + 49664);
    float* s_nr  = (float*)(sm + 53760);
    float* s_dn  = (float*)(sm + 54016);

    const int cr0 = m0 + (lane >> 2);
    const int cc0 = e0 + (lane & 3) * 2;

    // step A: wk=0 accs -> mat; norm partials; qa copy
    if (wk == 0) {
#pragma unroll
        for (int j = 0; j < 4; j++) {
            int c = cc0 + 8 * j;
            s_mat[cr0 * 66 + c]           = acc[j][0];
            s_mat[cr0 * 66 + c + 1]       = acc[j][1];
            s_mat[(cr0 + 8) * 66 + c]     = acc[j][2];
            s_mat[(cr0 + 8) * 66 + c + 1] = acc[j][3];
        }
    }
#pragma unroll
    for (int i = 0; i < 8; i++) s_np[n1 * 66 + dg + i] = nacc[i];
    if (tid < 256)
        ((float4*)s_qa)[tid] = ((const float4*)(g_qa + (size_t)b * DMODEL))[tid];
    __syncthreads();

    // step B: wk=1 accs merge; norm reduce
    if (wk == 1) {
#pragma unroll
        for (int j = 0; j < 4; j++) {
            int c = cc0 + 8 * j;
            s_mat[cr0 * 66 + c]           += acc[j][0];
            s_mat[cr0 * 66 + c + 1]       += acc[j][1];
            s_mat[(cr0 + 8) * 66 + c]     += acc[j][2];
            s_mat[(cr0 + 8) * 66 + c + 1] += acc[j][3];
        }
    }
    if (tid < DMEM) {
        float s = 0.f;
#pragma unroll 8
        for (int n = 0; n < 64; n++) s += s_np[n * 66 + tid];
        s_nr[tid] = s;
    }
    __syncthreads();

    // step C: denominators
    if (tid < NH) {
        float s = 0.f;
#pragma unroll 8
        for (int d = 0; d < DMEM; d++) s += s_qa[tid * DMEM + d] * s_nr[d];
        s_dn[tid] = s + 1e-5f;
    }
    __syncthreads();

    // step D: attn = qa @ mat / den   (each thread: heads h0 and h0+8, col e)
    {
        const int e = tid & 63;
        const int h0 = tid >> 6;          // 0..7
        float a0 = 0.f, a1 = 0.f;
#pragma unroll 8
        for (int d = 0; d < DMEM; d++) {
            float mv = s_mat[d * 66 + e];
            a0 += s_qa[h0 * DMEM + d] * mv;
            a1 += s_qa[(h0 + 8) * DMEM + d] * mv;
        }
        float* oa = g_attn + (size_t)b * DMODEL;
        oa[h0 * DMEM + e]       = a0 / s_dn[h0];
        oa[(h0 + 8) * DMEM + e] = a1 / s_dn[h0 + 8];
    }
}

// ============================================================
// HMMA split-K NT GEMM (known-good from R10)
// ============================================================
#define GA_H 0
#define GA_L 32768
#define GW_H 65536
#define GW_L 81920
#define G_SMEM 98304

__global__ __launch_bounds__(256, 1) void gemm_mma(
    const float* __restrict__ A_ext, const float* __restrict__ W, int mode)
{
    extern __shared__ __align__(1024) char sm[];
    const uint32_t sb = smem_u32(sm);
    const float* A = mode ? g_attn : A_ext;

    const int tid = threadIdx.x, lane = tid & 31, w = tid >> 5;
    const int bn = blockIdx.x * 64;
    const int kc0 = blockIdx.y * 128;

#pragma unroll
    for (int i = 0; i < 8; i++) {
        int item = tid + 256 * i;
        int row = item >> 4, c8 = item & 15;
        const float* p = A + (size_t)row * DMODEL + kc0 + c8 * 8;
        float4 f0 = *(const float4*)p, f1 = *(const float4*)(p + 4);
        uint32_t h[4], l[4];
        split2(make_float2(f0.x, f0.y), h[0], l[0]);
        split2(make_float2(f0.z, f0.w), h[1], l[1]);
        split2(make_float2(f1.x, f1.y), h[2], l[2]);
        split2(make_float2(f1.z, f1.w), h[3], l[3]);
        uint32_t off = (uint32_t)(row * 256 + c8 * 16);
        uint32_t sw = off ^ ((off >> 4) & 0x70);
        *(uint4*)(sm + GA_H + sw) = make_uint4(h[0], h[1], h[2], h[3]);
        *(uint4*)(sm + GA_L + sw) = make_uint4(l[0], l[1], l[2], l[3]);
    }
#pragma unroll
    for (int i = 0; i < 4; i++) {
        int item = tid + 256 * i;
        int row = item >> 4, c8 = item & 15;
        const float* p = W + (size_t)(bn + row) * DMODEL + kc0 + c8 * 8;
        float4 f0 = *(const float4*)p, f1 = *(const float4*)(p + 4);
        uint32_t h[4], l[4];
        split2(make_float2(f0.x, f0.y), h[0], l[0]);
        split2(make_float2(f0.z, f0.w), h[1], l[1]);
        split2(make_float2(f1.x, f1.y), h[2], l[2]);
        split2(make_float2(f1.z, f1.w), h[3], l[3]);
        uint32_t off = (uint32_t)(row * 256 + c8 * 16);
        uint32_t sw = off ^ ((off >> 4) & 0x70);
        *(uint4*)(sm + GW_H + sw) = make_uint4(h[0], h[1], h[2], h[3]);
        *(uint4*)(sm + GW_L + sw) = make_uint4(l[0], l[1], l[2], l[3]);
    }
    __syncthreads();

    const int m0 = w * 16;
    float acc[8][4];
#pragma unroll
    for (int i = 0; i < 8; i++)
#pragma unroll
        for (int j = 0; j < 4; j++) acc[i][j] = 0.f;

    const int rA = (lane & 7) + 8 * ((lane >> 3) & 1);
    const uint32_t baseA = (uint32_t)((m0 + rA) * 256 + (lane >> 4) * 16);
    const uint32_t maskA = (uint32_t)(lane & 7) << 4;
    const int rBl = (lane & 7) + 8 * (lane >> 4);
    const uint32_t hB = ((uint32_t)(lane >> 3) & 1) * 16;
    const uint32_t maskB = (uint32_t)(lane & 7) << 4;

#pragma unroll
    for (int ks = 0; ks < 8; ks++) {
        uint32_t swAa = (baseA + ks * 32) ^ maskA;
        uint32_t ah[4], al[4];
        ldsm4(ah, sb + GA_H + swAa);
        ldsm4(al, sb + GA_L + swAa);
#pragma unroll
        for (int j = 0; j < 4; j++) {
            uint32_t offB = (uint32_t)((16 * j + rBl) * 256 + ks * 32) + hB;
            uint32_t swB = offB ^ maskB;
            uint32_t wh[4], wl[4];
            ldsm4(wh, sb + GW_H + swB);
            ldsm4(wl, sb + GW_L + swB);
            mma16816(acc[2*j],     ah, wh[0], wh[1]);
            mma16816(acc[2*j + 1], ah, wh[2], wh[3]);
            mma16816(acc[2*j],     ah, wl[0], wl[1]);
            mma16816(acc[2*j + 1], ah, wl[2], wl[3]);
            mma16816(acc[2*j],     al, wh[0], wh[1]);
            mma16816(acc[2*j + 1], al, wh[2], wh[3]);
        }
    }

    float* P = g_gp + (size_t)blockIdx.y * (Bn * DMODEL);
    int r0 = m0 + (lane >> 2);
    int c0 = bn + (lane & 3) * 2;
#pragma unroll
    for (int jj = 0; jj < 8; jj++) {
        int c = c0 + 8 * jj;
        *(float2*)(P + (size_t)r0 * DMODEL + c)       = make_float2(acc[jj][0], acc[jj][1]);
        *(float2*)(P + (size_t)(r0 + 8) * DMODEL + c) = make_float2(acc[jj][2], acc[jj][3]);
    }
}

__global__ __launch_bounds__(256) void gemm_reduce(
    const float* __restrict__ bias, float* __restrict__ C_ext, int mode)
{
    int idx = blockIdx.x * 256 + threadIdx.x;
    float v = bias[idx & (DMODEL - 1)];
#pragma unroll
    for (int s = 0; s < 8; s++) v += g_gp[(size_t)s * Bn * DMODEL + idx];
    if (mode == 0) g_qa[idx] = fmaxf(v, 0.f);
    else           C_ext[idx] = v;
}

// ============================================================
extern "C" void kernel_launch(void* const* d_in, const int* in_sizes, int n_in,
                              void* d_out, int out_size)
{
    (void)in_sizes; (void)n_in; (void)out_size;
    const float* query     = (const float*)d_in[0];
    const float* addresses = (const float*)d_in[1];
    const float* memories  = (const float*)d_in[2];
    const float* Wq        = (const float*)d_in[3];
    const float* bq        = (const float*)d_in[4];
    const float* Wm        = (const float*)d_in[5];
    const float* bm        = (const float*)d_in[6];
    float* out = (float*)d_out;

    cudaFuncSetAttribute(gemm_mma, cudaFuncAttributeMaxDynamicSharedMemorySize, G_SMEM);
    cudaFuncSetAttribute(stage1_fused, cudaFuncAttributeMaxDynamicSharedMemorySize, S1_SMEM);

    // qa = relu(query @ Wq^T + bq)
    gemm_mma<<<dim3(16, 8), 256, G_SMEM>>>(query, Wq, 0);
    gemm_reduce<<<512, 256>>>(bq, nullptr, 0);
    // matrix + normalizer + attn (fused)
    stage1_fused<<<Bn, 512, S1_SMEM>>>(memories, addresses);
    // out = attn @ Wm^T + bm
    gemm_mma<<<dim3(16, 8), 256, G_SMEM>>>(nullptr, Wm, 1);
    gemm_reduce<<<512, 256>>>(bm, out, 1);
}

// round 14
// speedup vs baseline: 1.0045x; 1.0007x over previous
#include <cuda_runtime.h>
#include <cuda_bf16.h>
#include <cstdint>

#define Bn      128
#define DMODEL  1024
#define DMEM    64
#define NH      16
#define NMEM    4096

// ================= helpers =================
__device__ __forceinline__ uint32_t smem_u32(const void* p) {
    uint32_t a;
    asm("{ .reg .u64 t; cvta.to.shared.u64 t, %1; cvt.u32.u64 %0, t; }"
        : "=r"(a) : "l"(p));
    return a;
}
__device__ __forceinline__ void ldsm4(uint32_t* r, uint32_t a) {
    asm volatile("ldmatrix.sync.aligned.m8n8.x4.shared.b16 {%0,%1,%2,%3}, [%4];"
                 : "=r"(r[0]), "=r"(r[1]), "=r"(r[2]), "=r"(r[3]) : "r"(a));
}
__device__ __forceinline__ void ldsm4t(uint32_t* r, uint32_t a) {
    asm volatile("ldmatrix.sync.aligned.m8n8.x4.trans.shared.b16 {%0,%1,%2,%3}, [%4];"
                 : "=r"(r[0]), "=r"(r[1]), "=r"(r[2]), "=r"(r[3]) : "r"(a));
}
__device__ __forceinline__ void mma16816(float* c, const uint32_t* a,
                                         uint32_t b0, uint32_t b1) {
    asm volatile(
        "mma.sync.aligned.m16n8k16.row.col.f32.bf16.bf16.f32 "
        "{%0,%1,%2,%3}, {%4,%5,%6,%7}, {%8,%9}, {%0,%1,%2,%3};"
        : "+f"(c[0]), "+f"(c[1]), "+f"(c[2]), "+f"(c[3])
        : "r"(a[0]), "r"(a[1]), "r"(a[2]), "r"(a[3]), "r"(b0), "r"(b1));
}
__device__ __forceinline__ unsigned b2u(__nv_bfloat162 v) {
    return *reinterpret_cast<unsigned*>(&v);
}
__device__ __forceinline__ void split2(float2 f, uint32_t& hi, uint32_t& lo) {
    __nv_bfloat162 h = __float22bfloat162_rn(f);
    float2 hf = __bfloat1622float2(h);
    __nv_bfloat162 l = __float22bfloat162_rn(make_float2(f.x - hf.x, f.y - hf.y));
    hi = b2u(h);
    lo = b2u(l);
}

// ================= scratch =================
__device__ float g_qa[Bn * DMODEL];
__device__ float g_attn[Bn * DMODEL];
__device__ float g_gp[8 * Bn * DMODEL];      // split-K partials (4 MB)

// ============================================================
// Stage 1 + attn read, fused (HMMA). Per batch b:
//   matrix[d][e] = sum_n relu(mem+addr)[n][d] * mem[n][e]   (smem only)
//   norm[d]      = sum_n k[n][d]
//   attn[h][e]   = (qa[h] . matrix[:,e]) / (qa[h] . norm + 1e-5)
// 512 threads = 16 warps: (wd 0..3) x (we 0..1) x (wk 0..1 k-split).
// Double-buffered bf16 tiles [n=64][feat=64] (kh,kl,mh,ml), XOR-swizzled.
// ============================================================
#define S1_SMEM 65536

__global__ __launch_bounds__(512, 1) void stage1_fused(
    const float* __restrict__ mem, const float* __restrict__ addr)
{
    extern __shared__ __align__(1024) char sm[];
    const uint32_t sb = smem_u32(sm);
    const int b = blockIdx.x, tid = threadIdx.x;
    const int lane = tid & 31, w = tid >> 5;

    // tile offsets within one buffer; buffer stride 32768
    const uint32_t KH = 0, KL = 8192, MH = 16384, ML = 24576;

    // ---- conversion mapping: thread -> (n row, 8-float d group) ----
    const int n1 = tid >> 3;                 // 0..63
    const int dg = (tid & 7) << 3;           // float col base, 0..56
    const uint32_t swc = ((uint32_t)(n1 * 128 + dg * 2)) ^ ((uint32_t)(n1 & 7) << 4);

    // ---- mma mapping ----
    const int wd = w & 3, we = (w >> 2) & 1, wk = w >> 3;
    const int m0 = wd * 16;                  // d rows
    const int e0 = we * 32;                  // e cols
    const uint32_t lm = (uint32_t)(lane & 7) << 4;
    const int rA = (lane & 7) + 8 * (lane >> 4);
    const int cA = m0 + 8 * ((lane >> 3) & 1);
    const uint32_t swA = ((uint32_t)(rA * 128 + cA * 2)) ^ lm;
    const int rB = (lane & 7) + 8 * ((lane >> 3) & 1);
    const int cB = e0 + 8 * (lane >> 4);
    const uint32_t swB0 = ((uint32_t)(rB * 128 + cB * 2)) ^ lm;
    const uint32_t swB1 = ((uint32_t)(rB * 128 + (cB + 16) * 2)) ^ lm;

    float acc[4][4];
#pragma unroll
    for (int i = 0; i < 4; i++)
#pragma unroll
        for (int j = 0; j < 4; j++) acc[i][j] = 0.f;

    float nacc[8];
#pragma unroll
    for (int i = 0; i < 8; i++) nacc[i] = 0.f;

    const float* mb = mem + (size_t)b * NMEM * DMEM;

    float4 m4[2], a4[2];
    auto ldg_chunk = [&](int ch) {
        const float* pm = mb   + ((size_t)ch * 64 + n1) * DMEM + dg;
        const float* pa = addr + ((size_t)ch * 64 + n1) * DMEM + dg;
        m4[0] = *(const float4*)pm;
        m4[1] = *(const float4*)(pm + 4);
        a4[0] = *(const float4*)pa;
        a4[1] = *(const float4*)(pa + 4);
    };
    auto cvt_store = [&](int buf) {
        float mv[8], kv[8];
#pragma unroll
        for (int j = 0; j < 2; j++) {
            mv[4*j+0] = m4[j].x; mv[4*j+1] = m4[j].y;
            mv[4*j+2] = m4[j].z; mv[4*j+3] = m4[j].w;
            kv[4*j+0] = fmaxf(m4[j].x + a4[j].x, 0.f);
            kv[4*j+1] = fmaxf(m4[j].y + a4[j].y, 0.f);
            kv[4*j+2] = fmaxf(m4[j].z + a4[j].z, 0.f);
            kv[4*j+3] = fmaxf(m4[j].w + a4[j].w, 0.f);
        }
#pragma unroll
        for (int i = 0; i < 8; i++) nacc[i] += kv[i];
        uint32_t kh[4], kl[4], mh[4], ml[4];
#pragma unroll
        for (int p = 0; p < 4; p++) {
            split2(make_float2(kv[2*p], kv[2*p+1]), kh[p], kl[p]);
            split2(make_float2(mv[2*p], mv[2*p+1]), mh[p], ml[p]);
        }
        char* base = sm + buf * 32768;
        *(uint4*)(base + KH + swc) = make_uint4(kh[0], kh[1], kh[2], kh[3]);
        *(uint4*)(base + KL + swc) = make_uint4(kl[0], kl[1], kl[2], kl[3]);
        *(uint4*)(base + MH + swc) = make_uint4(mh[0], mh[1], mh[2], mh[3]);
        *(uint4*)(base + ML + swc) = make_uint4(ml[0], ml[1], ml[2], ml[3]);
    };

    ldg_chunk(0);
    cvt_store(0);
    __syncthreads();

    for (int ch = 0; ch < NMEM / 64; ch++) {
        const uint32_t tb = sb + (uint32_t)(ch & 1) * 32768;
        if (ch + 1 < NMEM / 64) ldg_chunk(ch + 1);

        // ---- mma: this warp handles ksteps {2*wk, 2*wk+1} ----
#pragma unroll
        for (int ks = 0; ks < 2; ks++) {
            const uint32_t ko = 2048u * (2 * wk + ks);
            uint32_t ah[4], al[4], bh0[4], bh1[4], bl0[4], bl1[4];
            ldsm4t(ah,  tb + KH + swA + ko);
            ldsm4t(al,  tb + KL + swA + ko);
            ldsm4t(bh0, tb + MH + swB0 + ko);
            ldsm4t(bh1, tb + MH + swB1 + ko);
            ldsm4t(bl0, tb + ML + swB0 + ko);
            ldsm4t(bl1, tb + ML + swB1 + ko);
            mma16816(acc[0], ah, bh0[0], bh0[1]);
            mma16816(acc[1], ah, bh0[2], bh0[3]);
            mma16816(acc[2], ah, bh1[0], bh1[1]);
            mma16816(acc[3], ah, bh1[2], bh1[3]);
            mma16816(acc[0], ah, bl0[0], bl0[1]);
            mma16816(acc[1], ah, bl0[2], bl0[3]);
            mma16816(acc[2], ah, bl1[0], bl1[1]);
            mma16816(acc[3], ah, bl1[2], bl1[3]);
            mma16816(acc[0], al, bh0[0], bh0[1]);
            mma16816(acc[1], al, bh0[2], bh0[3]);
            mma16816(acc[2], al, bh1[0], bh1[1]);
            mma16816(acc[3], al, bh1[2], bh1[3]);
        }

        if (ch + 1 < NMEM / 64) cvt_store((ch + 1) & 1);
        __syncthreads();
    }

    // ================= fused epilogue =================
    // smem reuse (all tiles dead): mat[64][66] @0, npart[64][66] @32768,
    // qa[16][64] @49664, norm[64] @53760, den[16] @54016
    float* s_mat = (float*)sm;
    float* s_np  = (float*)(sm + 32768);
    float* s_qa  = (float*)(sm + 49664);
    float* s_nr  = (float*)(sm + 53760);
    float* s_dn  = (float*)(sm + 54016);

    const int cr0 = m0 + (lane >> 2);
    const int cc0 = e0 + (lane & 3) * 2;

    // step A: wk=0 accs -> mat; norm partials; qa copy
    if (wk == 0) {
#pragma unroll
        for (int j = 0; j < 4; j++) {
            int c = cc0 + 8 * j;
            s_mat[cr0 * 66 + c]           = acc[j][0];
            s_mat[cr0 * 66 + c + 1]       = acc[j][1];
            s_mat[(cr0 + 8) * 66 + c]     = acc[j][2];
            s_mat[(cr0 + 8) * 66 + c + 1] = acc[j][3];
        }
    }
#pragma unroll
    for (int i = 0; i < 8; i++) s_np[n1 * 66 + dg + i] = nacc[i];
    if (tid < 256)
        ((float4*)s_qa)[tid] = ((const float4*)(g_qa + (size_t)b * DMODEL))[tid];
    __syncthreads();

    // step B: wk=1 accs merge; norm reduce
    if (wk == 1) {
#pragma unroll
        for (int j = 0; j < 4; j++) {
            int c = cc0 + 8 * j;
            s_mat[cr0 * 66 + c]           += acc[j][0];
            s_mat[cr0 * 66 + c + 1]       += acc[j][1];
            s_mat[(cr0 + 8) * 66 + c]     += acc[j][2];
            s_mat[(cr0 + 8) * 66 + c + 1] += acc[j][3];
        }
    }
    if (tid < DMEM) {
        float s = 0.f;
#pragma unroll 8
        for (int n = 0; n < 64; n++) s += s_np[n * 66 + tid];
        s_nr[tid] = s;
    }
    __syncthreads();

    // step C: denominators
    if (tid < NH) {
        float s = 0.f;
#pragma unroll 8
        for (int d = 0; d < DMEM; d++) s += s_qa[tid * DMEM + d] * s_nr[d];
        s_dn[tid] = s + 1e-5f;
    }
    __syncthreads();

    // step D: attn = qa @ mat / den   (each thread: heads h0 and h0+8, col e)
    {
        const int e = tid & 63;
        const int h0 = tid >> 6;          // 0..7
        float a0 = 0.f, a1 = 0.f;
#pragma unroll 8
        for (int d = 0; d < DMEM; d++) {
            float mv = s_mat[d * 66 + e];
            a0 += s_qa[h0 * DMEM + d] * mv;
            a1 += s_qa[(h0 + 8) * DMEM + d] * mv;
        }
        float* oa = g_attn + (size_t)b * DMODEL;
        oa[h0 * DMEM + e]       = a0 / s_dn[h0];
        oa[(h0 + 8) * DMEM + e] = a1 / s_dn[h0 + 8];
    }
}

// ============================================================
// HMMA split-K NT GEMM (known-good from R10)
// ============================================================
#define GA_H 0
#define GA_L 32768
#define GW_H 65536
#define GW_L 81920
#define G_SMEM 98304

__global__ __launch_bounds__(256, 1) void gemm_mma(
    const float* __restrict__ A_ext, const float* __restrict__ W, int mode)
{
    extern __shared__ __align__(1024) char sm[];
    const uint32_t sb = smem_u32(sm);
    const float* A = mode ? g_attn : A_ext;

    const int tid = threadIdx.x, lane = tid & 31, w = tid >> 5;
    const int bn = blockIdx.x * 64;
    const int kc0 = blockIdx.y * 128;

#pragma unroll
    for (int i = 0; i < 8; i++) {
        int item = tid + 256 * i;
        int row = item >> 4, c8 = item & 15;
        const float* p = A + (size_t)row * DMODEL + kc0 + c8 * 8;
        float4 f0 = *(const float4*)p, f1 = *(const float4*)(p + 4);
        uint32_t h[4], l[4];
        split2(make_float2(f0.x, f0.y), h[0], l[0]);
        split2(make_float2(f0.z, f0.w), h[1], l[1]);
        split2(make_float2(f1.x, f1.y), h[2], l[2]);
        split2(make_float2(f1.z, f1.w), h[3], l[3]);
        uint32_t off = (uint32_t)(row * 256 + c8 * 16);
        uint32_t sw = off ^ ((off >> 4) & 0x70);
        *(uint4*)(sm + GA_H + sw) = make_uint4(h[0], h[1], h[2], h[3]);
        *(uint4*)(sm + GA_L + sw) = make_uint4(l[0], l[1], l[2], l[3]);
    }
#pragma unroll
    for (int i = 0; i < 4; i++) {
        int item = tid + 256 * i;
        int row = item >> 4, c8 = item & 15;
        const float* p = W + (size_t)(bn + row) * DMODEL + kc0 + c8 * 8;
        float4 f0 = *(const float4*)p, f1 = *(const float4*)(p + 4);
        uint32_t h[4], l[4];
        split2(make_float2(f0.x, f0.y), h[0], l[0]);
        split2(make_float2(f0.z, f0.w), h[1], l[1]);
        split2(make_float2(f1.x, f1.y), h[2], l[2]);
        split2(make_float2(f1.z, f1.w), h[3], l[3]);
        uint32_t off = (uint32_t)(row * 256 + c8 * 16);
        uint32_t sw = off ^ ((off >> 4) & 0x70);
        *(uint4*)(sm + GW_H + sw) = make_uint4(h[0], h[1], h[2], h[3]);
        *(uint4*)(sm + GW_L + sw) = make_uint4(l[0], l[1], l[2], l[3]);
    }
    __syncthreads();

    const int m0 = w * 16;
    float acc[8][4];
#pragma unroll
    for (int i = 0; i < 8; i++)
#pragma unroll
        for (int j = 0; j < 4; j++) acc[i][j] = 0.f;

    const int rA = (lane & 7) + 8 * ((lane >> 3) & 1);
    const uint32_t baseA = (uint32_t)((m0 + rA) * 256 + (lane >> 4) * 16);
    const uint32_t maskA = (uint32_t)(lane & 7) << 4;
    const int rBl = (lane & 7) + 8 * (lane >> 4);
    const uint32_t hB = ((uint32_t)(lane >> 3) & 1) * 16;
    const uint32_t maskB = (uint32_t)(lane & 7) << 4;

#pragma unroll
    for (int ks = 0; ks < 8; ks++) {
        uint32_t swAa = (baseA + ks * 32) ^ maskA;
        uint32_t ah[4], al[4];
        ldsm4(ah, sb + GA_H + swAa);
        ldsm4(al, sb + GA_L + swAa);
#pragma unroll
        for (int j = 0; j < 4; j++) {
            uint32_t offB = (uint32_t)((16 * j + rBl) * 256 + ks * 32) + hB;
            uint32_t swB = offB ^ maskB;
            uint32_t wh[4], wl[4];
            ldsm4(wh, sb + GW_H + swB);
            ldsm4(wl, sb + GW_L + swB);
            mma16816(acc[2*j],     ah, wh[0], wh[1]);
            mma16816(acc[2*j + 1], ah, wh[2], wh[3]);
            mma16816(acc[2*j],     ah, wl[0], wl[1]);
            mma16816(acc[2*j + 1], ah, wl[2], wl[3]);
            mma16816(acc[2*j],     al, wh[0], wh[1]);
            mma16816(acc[2*j + 1], al, wh[2], wh[3]);
        }
    }

    float* P = g_gp + (size_t)blockIdx.y * (Bn * DMODEL);
    int r0 = m0 + (lane >> 2);
    int c0 = bn + (lane & 3) * 2;
#pragma unroll
    for (int jj = 0; jj < 8; jj++) {
        int c = c0 + 8 * jj;
        *(float2*)(P + (size_t)r0 * DMODEL + c)       = make_float2(acc[jj][0], acc[jj][1]);
        *(float2*)(P + (size_t)(r0 + 8) * DMODEL + c) = make_float2(acc[jj][2], acc[jj][3]);
    }
}

__global__ __launch_bounds__(256) void gemm_reduce(
    const float* __restrict__ bias, float* __restrict__ C_ext, int mode)
{
    int idx = blockIdx.x * 256 + threadIdx.x;
    float v = bias[idx & (DMODEL - 1)];
#pragma unroll
    for (int s = 0; s < 8; s++) v += g_gp[(size_t)s * Bn * DMODEL + idx];
    if (mode == 0) g_qa[idx] = fmaxf(v, 0.f);
    else           C_ext[idx] = v;
}

// ============================================================
extern "C" void kernel_launch(void* const* d_in, const int* in_sizes, int n_in,
                              void* d_out, int out_size)
{
    (void)in_sizes; (void)n_in; (void)out_size;
    const float* query     = (const float*)d_in[0];
    const float* addresses = (const float*)d_in[1];
    const float* memories  = (const float*)d_in[2];
    const float* Wq        = (const float*)d_in[3];
    const float* bq        = (const float*)d_in[4];
    const float* Wm        = (const float*)d_in[5];
    const float* bm        = (const float*)d_in[6];
    float* out = (float*)d_out;

    cudaFuncSetAttribute(gemm_mma, cudaFuncAttributeMaxDynamicSharedMemorySize, G_SMEM);
    cudaFuncSetAttribute(stage1_fused, cudaFuncAttributeMaxDynamicSharedMemorySize, S1_SMEM);

    // qa = relu(query @ Wq^T + bq)
    gemm_mma<<<dim3(16, 8), 256, G_SMEM>>>(query, Wq, 0);
    gemm_reduce<<<512, 256>>>(bq, nullptr, 0);
    // matrix + normalizer + attn (fused)
    stage1_fused<<<Bn, 512, S1_SMEM>>>(memories, addresses);
    // out = attn @ Wm^T + bm
    gemm_mma<<<dim3(16, 8), 256, G_SMEM>>>(nullptr, Wm, 1);
    gemm_reduce<<<512, 256>>>(bm, out, 1);
}